// round 9
// baseline (speedup 1.0000x reference)
#include <cuda_runtime.h>
#include <cuda_bf16.h>
#include <math.h>

#define N_NODES 100000
#define N_EDGES 1600000
#define F_IN   128
#define H1     200
#define H2     50
#define C_OUT  10
#define MAXDEG 128

typedef __nv_bfloat16 bf16;

// ---------------- scratch -----------------------------------------------------
__device__ int   g_cnt[N_NODES];
__device__ int   g_bucket[(size_t)N_NODES * MAXDEG];
__device__ bf16  g_xh  [(size_t)N_NODES * F_IN];
__device__ bf16  g_xl  [(size_t)N_NODES * F_IN];
__device__ bf16  g_a1h [(size_t)N_NODES * F_IN];
__device__ bf16  g_a1l [(size_t)N_NODES * F_IN];
__device__ float g_h1f [(size_t)N_NODES * H1];
__device__ bf16  g_h1h [(size_t)N_NODES * H1];
__device__ bf16  g_h1l [(size_t)N_NODES * H1];
__device__ bf16  g_a2h [(size_t)N_NODES * H1];
__device__ bf16  g_a2l [(size_t)N_NODES * H1];
__device__ float g_h2  [(size_t)N_NODES * H2];
__device__ float g_agg3[(size_t)N_NODES * H2];
// transposed, split weights: [NN, K]
__device__ bf16  g_w1lh[(size_t)H1 * F_IN], g_w1ll[(size_t)H1 * F_IN];
__device__ bf16  g_w1rh[(size_t)H1 * F_IN], g_w1rl[(size_t)H1 * F_IN];
__device__ bf16  g_w2lh[(size_t)H2 * H1],   g_w2ll[(size_t)H2 * H1];
__device__ bf16  g_w2rh[(size_t)H2 * H1],   g_w2rl[(size_t)H2 * H1];

__device__ __forceinline__ void bf16_split(float x, bf16& h, bf16& l) {
    h = __float2bfloat16(x);
    l = __float2bfloat16(x - __bfloat162float(h));
}

__device__ __forceinline__ unsigned pack2(bf16 a, bf16 b) {
    __nv_bfloat162 p = __halves2bfloat162(a, b);
    return *reinterpret_cast<unsigned*>(&p);
}

// cp.async 16B with zero-fill when !ok
__device__ __forceinline__ void cp16(void* dst, const void* src, bool ok) {
    unsigned d = (unsigned)__cvta_generic_to_shared(dst);
    int ss = ok ? 16 : 0;
    asm volatile("cp.async.ca.shared.global [%0], [%1], 16, %2;"
                 :: "r"(d), "l"(src), "r"(ss));
}
__device__ __forceinline__ void cp_commit() {
    asm volatile("cp.async.commit_group;");
}
__device__ __forceinline__ void cp_wait1() {
    asm volatile("cp.async.wait_group 1;");
}

// ---------------- bucket build ------------------------------------------------
__global__ void zero_cnt_kernel() {
    int i = blockIdx.x * blockDim.x + threadIdx.x;
    if (i < N_NODES) g_cnt[i] = 0;
}

__global__ void bucket_build_kernel(const int* __restrict__ src,
                                    const int* __restrict__ dst) {
    int e = blockIdx.x * blockDim.x + threadIdx.x;
    if (e >= N_EDGES) return;
    int d = dst[e];
    int p = atomicAdd(&g_cnt[d], 1);
    if (p < MAXDEG) g_bucket[(size_t)d * MAXDEG + p] = src[e];
}

// ---------------- one-time splits --------------------------------------------
__global__ void split_x_kernel(const float* __restrict__ x,
                               bf16* __restrict__ xh, bf16* __restrict__ xl) {
    int i = blockIdx.x * blockDim.x + threadIdx.x;
    if (i >= N_NODES * F_IN / 4) return;
    float4 v = ((const float4*)x)[i];
    bf16 h[4], l[4];
    bf16_split(v.x, h[0], l[0]);
    bf16_split(v.y, h[1], l[1]);
    bf16_split(v.z, h[2], l[2]);
    bf16_split(v.w, h[3], l[3]);
    uint2 uh, ul;
    uh.x = pack2(h[0], h[1]); uh.y = pack2(h[2], h[3]);
    ul.x = pack2(l[0], l[1]); ul.y = pack2(l[2], l[3]);
    *(uint2*)(xh + (size_t)i * 4) = uh;
    *(uint2*)(xl + (size_t)i * 4) = ul;
}

// W [K,NN] row-major -> Wt hi/lo [NN,K]
__global__ void split_wt_kernel(const float* __restrict__ W,
                                bf16* __restrict__ th, bf16* __restrict__ tl,
                                int K, int NN) {
    int j = blockIdx.x * blockDim.x + threadIdx.x;
    if (j >= K * NN) return;
    int n = j / K, k = j - n * K;
    bf16 h, l;
    bf16_split(W[(size_t)k * NN + n], h, l);
    th[j] = h;
    tl[j] = l;
}

__device__ __forceinline__ void fmax4(float4& m, float4 v) {
    m.x = fmaxf(m.x, v.x);
    m.y = fmaxf(m.y, v.y);
    m.z = fmaxf(m.z, v.z);
    m.w = fmaxf(m.w, v.w);
}
__device__ __forceinline__ void fmax2(float2& m, float2 v) {
    m.x = fmaxf(m.x, v.x);
    m.y = fmaxf(m.y, v.y);
}

// ---------------- aggregation: fp32 gather, split-bf16 output (round-7 form) --
template <int F>
__global__ void agg_split_kernel(const float* __restrict__ x,
                                 bf16* __restrict__ oh, bf16* __restrict__ ol) {
    constexpr int C4 = F / 4;
    constexpr int RV = (C4 + 31) / 32;

    int gwarp = (blockIdx.x * blockDim.x + threadIdx.x) >> 5;
    int lane  = threadIdx.x & 31;
    if (gwarp >= N_NODES) return;

    int c = g_cnt[gwarp];
    if (c > MAXDEG) c = MAXDEG;

    float4 m[RV];
#pragma unroll
    for (int r = 0; r < RV; r++)
        m[r] = make_float4(-INFINITY, -INFINITY, -INFINITY, -INFINITY);

    const int* bk = g_bucket + (size_t)gwarp * MAXDEG;
    int i = 0;
    for (; i + 3 < c; i += 4) {
        int s0 = bk[i], s1 = bk[i + 1], s2 = bk[i + 2], s3 = bk[i + 3];
        const float4* p0 = (const float4*)(x + (size_t)s0 * F);
        const float4* p1 = (const float4*)(x + (size_t)s1 * F);
        const float4* p2 = (const float4*)(x + (size_t)s2 * F);
        const float4* p3 = (const float4*)(x + (size_t)s3 * F);
#pragma unroll
        for (int r = 0; r < RV; r++) {
            int ch = lane + r * 32;
            if (ch < C4) {
                float4 v0 = p0[ch], v1 = p1[ch], v2 = p2[ch], v3 = p3[ch];
                fmax4(v0, v1); fmax4(v2, v3);
                fmax4(v0, v2);
                fmax4(m[r], v0);
            }
        }
    }
    for (; i < c; i++) {
        const float4* p0 = (const float4*)(x + (size_t)bk[i] * F);
#pragma unroll
        for (int r = 0; r < RV; r++) {
            int ch = lane + r * 32;
            if (ch < C4) fmax4(m[r], p0[ch]);
        }
    }

#pragma unroll
    for (int r = 0; r < RV; r++) {
        int ch = lane + r * 32;
        if (ch < C4) {
            float v[4] = {m[r].x, m[r].y, m[r].z, m[r].w};
            bf16 hh[4], ll[4];
#pragma unroll
            for (int q = 0; q < 4; q++) {
                float vv = (c == 0) ? 0.f : v[q];
                bf16_split(vv, hh[q], ll[q]);
            }
            uint2 uh, ul;
            uh.x = pack2(hh[0], hh[1]); uh.y = pack2(hh[2], hh[3]);
            ul.x = pack2(ll[0], ll[1]); ul.y = pack2(ll[2], ll[3]);
            *(uint2*)(oh + (size_t)gwarp * F + ch * 4) = uh;
            *(uint2*)(ol + (size_t)gwarp * F + ch * 4) = ul;
        }
    }
}

// ---------------- fp32 aggregation (layer 3, H2=50) --------------------------
template <int F>
__global__ void agg_kernel(const float* __restrict__ x, float* __restrict__ agg) {
    constexpr int C2 = F / 2;
    constexpr int RV = (C2 + 31) / 32;

    int gwarp = (blockIdx.x * blockDim.x + threadIdx.x) >> 5;
    int lane  = threadIdx.x & 31;
    if (gwarp >= N_NODES) return;

    int c = g_cnt[gwarp];
    if (c > MAXDEG) c = MAXDEG;

    float2 m[RV];
#pragma unroll
    for (int r = 0; r < RV; r++) { m[r].x = -INFINITY; m[r].y = -INFINITY; }

    const int* bk = g_bucket + (size_t)gwarp * MAXDEG;
    int i = 0;
    for (; i + 3 < c; i += 4) {
        int s0 = bk[i], s1 = bk[i + 1], s2 = bk[i + 2], s3 = bk[i + 3];
        const float2* p0 = (const float2*)(x + (size_t)s0 * F);
        const float2* p1 = (const float2*)(x + (size_t)s1 * F);
        const float2* p2 = (const float2*)(x + (size_t)s2 * F);
        const float2* p3 = (const float2*)(x + (size_t)s3 * F);
#pragma unroll
        for (int r = 0; r < RV; r++) {
            int ch = lane + r * 32;
            if (ch < C2) {
                float2 v0 = p0[ch], v1 = p1[ch], v2 = p2[ch], v3 = p3[ch];
                fmax2(v0, v1); fmax2(v2, v3);
                fmax2(v0, v2);
                fmax2(m[r], v0);
            }
        }
    }
    for (; i < c; i++) {
        const float2* p0 = (const float2*)(x + (size_t)bk[i] * F);
#pragma unroll
        for (int r = 0; r < RV; r++) {
            int ch = lane + r * 32;
            if (ch < C2) fmax2(m[r], p0[ch]);
        }
    }

    float2* out = (float2*)(agg + (size_t)gwarp * F);
#pragma unroll
    for (int r = 0; r < RV; r++) {
        int ch = lane + r * 32;
        if (ch < C2) out[ch] = (c == 0) ? make_float2(0.f, 0.f) : m[r];
    }
}

// ---------------- all-bf16 tensor-core dual GEMM, cp.async 3-stage -----------
#define MMA16816(d, a, b0, b1)                                                \
    asm volatile(                                                             \
        "mma.sync.aligned.m16n8k16.row.col.f32.bf16.bf16.f32 "                \
        "{%0,%1,%2,%3}, {%4,%5,%6,%7}, {%8,%9}, {%0,%1,%2,%3};"               \
        : "+f"(d[0]), "+f"(d[1]), "+f"(d[2]), "+f"(d[3])                      \
        : "r"(a[0]), "r"(a[1]), "r"(a[2]), "r"(a[3]), "r"(b0), "r"(b1))

// All operands pre-split bf16. A [M,K] row-major hi/lo; B (=W^T) [NN,K]
// row-major hi/lo. BM=128 (WM=4), BN=WN*NT*8, 256 threads, 3-stage cp.async.
template <int WN, int NT, bool SPLIT_OUT>
__global__ __launch_bounds__(256, 2)
void gemm_cp(const bf16* __restrict__ Ah1, const bf16* __restrict__ Al1,
             const bf16* __restrict__ Ah2, const bf16* __restrict__ Al2,
             const bf16* __restrict__ Bh1, const bf16* __restrict__ Bl1,
             const bf16* __restrict__ Bh2, const bf16* __restrict__ Bl2,
             const float* __restrict__ bias,
             float* __restrict__ outf,
             bf16* __restrict__ outh, bf16* __restrict__ outl,
             int M, int K, int NN) {
    constexpr int WM = 4;
    constexpr int BM = 128;
    constexpr int BN = WN * NT * 8;
    constexpr int LDSTR = 24;
    constexpr int ST = 3;

    extern __shared__ __align__(16) char smem_raw[];
    bf16* Ash = (bf16*)smem_raw;                 // ST * BM * LDSTR
    bf16* Asl = Ash + ST * BM * LDSTR;
    bf16* Bsh = Asl + ST * BM * LDSTR;           // ST * BN * LDSTR
    bf16* Bsl = Bsh + ST * BN * LDSTR;

    int tid = threadIdx.x;
    int lane = tid & 31;
    int wid = tid >> 5;
    int wm = wid % WM;
    int wn = wid / WM;
    int g  = lane >> 2;
    int tg = lane & 3;

    int rowBase = blockIdx.y * BM;
    int colBase = blockIdx.x * BN;

    int npt  = (K + 15) >> 4;
    int totT = 2 * npt;

    const int r_  = tid >> 1;            // A row in tile
    const int kh_ = (tid & 1) * 8;       // k chunk (0 or 8)
    const int aRow = rowBase + r_;
    const int bn_ = tid >> 1;            // B row in tile (valid if < BN)
    const int gN  = colBase + bn_;

    float acc[2][NT][4];
#pragma unroll
    for (int mt = 0; mt < 2; mt++)
#pragma unroll
        for (int nt = 0; nt < NT; nt++)
#pragma unroll
            for (int q = 0; q < 4; q++) acc[mt][nt][q] = 0.f;

    auto issue = [&](int t, int s) {
        const bf16 *Ah, *Al, *Bh, *Bl; int ko;
        if (t < npt) { Ah = Ah1; Al = Al1; Bh = Bh1; Bl = Bl1; ko = t << 4; }
        else { Ah = Ah2; Al = Al2; Bh = Bh2; Bl = Bl2; ko = (t - npt) << 4; }
        int gk = ko + kh_;
        bool okA = (aRow < M) && (gk + 8 <= K);
        const bf16* sah = okA ? (Ah + (size_t)aRow * K + gk) : Ah;
        const bf16* sal = okA ? (Al + (size_t)aRow * K + gk) : Al;
        cp16(&Ash[s * BM * LDSTR + r_ * LDSTR + kh_], sah, okA);
        cp16(&Asl[s * BM * LDSTR + r_ * LDSTR + kh_], sal, okA);
        if (bn_ < BN) {
            bool okB = (gN < NN) && (gk + 8 <= K);
            const bf16* sbh = okB ? (Bh + (size_t)gN * K + gk) : Bh;
            const bf16* sbl = okB ? (Bl + (size_t)gN * K + gk) : Bl;
            cp16(&Bsh[s * BN * LDSTR + bn_ * LDSTR + kh_], sbh, okB);
            cp16(&Bsl[s * BN * LDSTR + bn_ * LDSTR + kh_], sbl, okB);
        }
    };

    auto compute = [&](int s) {
        const bf16* As_h = Ash + s * BM * LDSTR;
        const bf16* As_l = Asl + s * BM * LDSTR;
        const bf16* Bs_h = Bsh + s * BN * LDSTR;
        const bf16* Bs_l = Bsl + s * BN * LDSTR;
        unsigned afh[2][4], afl[2][4];
#pragma unroll
        for (int mt = 0; mt < 2; mt++) {
            int r0 = wm * 32 + mt * 16 + g;
            afh[mt][0] = *(const unsigned*)&As_h[(r0)     * LDSTR + 2 * tg];
            afh[mt][1] = *(const unsigned*)&As_h[(r0 + 8) * LDSTR + 2 * tg];
            afh[mt][2] = *(const unsigned*)&As_h[(r0)     * LDSTR + 2 * tg + 8];
            afh[mt][3] = *(const unsigned*)&As_h[(r0 + 8) * LDSTR + 2 * tg + 8];
            afl[mt][0] = *(const unsigned*)&As_l[(r0)     * LDSTR + 2 * tg];
            afl[mt][1] = *(const unsigned*)&As_l[(r0 + 8) * LDSTR + 2 * tg];
            afl[mt][2] = *(const unsigned*)&As_l[(r0)     * LDSTR + 2 * tg + 8];
            afl[mt][3] = *(const unsigned*)&As_l[(r0 + 8) * LDSTR + 2 * tg + 8];
        }
#pragma unroll
        for (int nt = 0; nt < NT; nt++) {
            int c0 = (wn * NT + nt) * 8 + g;
            unsigned bh0 = *(const unsigned*)&Bs_h[c0 * LDSTR + 2 * tg];
            unsigned bh1 = *(const unsigned*)&Bs_h[c0 * LDSTR + 2 * tg + 8];
            unsigned bl0 = *(const unsigned*)&Bs_l[c0 * LDSTR + 2 * tg];
            unsigned bl1 = *(const unsigned*)&Bs_l[c0 * LDSTR + 2 * tg + 8];
#pragma unroll
            for (int mt = 0; mt < 2; mt++) {
                MMA16816(acc[mt][nt], afh[mt], bh0, bh1);
                MMA16816(acc[mt][nt], afh[mt], bl0, bl1);
                MMA16816(acc[mt][nt], afl[mt], bh0, bh1);
            }
        }
    };

    // 3-stage pipeline, one __syncthreads per tile
    issue(0, 0); cp_commit();
    if (totT > 1) issue(1, 1);
    cp_commit();

    for (int t = 0; t < totT; t++) {
        cp_wait1();
        __syncthreads();
        if (t + 2 < totT) issue(t + 2, (t + 2) % ST);
        cp_commit();
        compute(t % ST);
    }

    // ---- epilogue ----
#pragma unroll
    for (int mt = 0; mt < 2; mt++) {
#pragma unroll
        for (int nt = 0; nt < NT; nt++) {
            int col = colBase + (wn * NT + nt) * 8 + 2 * tg;
            if (col >= NN) continue;
            float2 bv = *(const float2*)(bias + col);
            int row0 = rowBase + wm * 32 + mt * 16 + g;
            int row1 = row0 + 8;
            float v0x = acc[mt][nt][0] + bv.x, v0y = acc[mt][nt][1] + bv.y;
            float v1x = acc[mt][nt][2] + bv.x, v1y = acc[mt][nt][3] + bv.y;
            if (row0 < M) {
                if (SPLIT_OUT) {
                    bf16 hx, lx, hy, ly;
                    bf16_split(v0x, hx, lx); bf16_split(v0y, hy, ly);
                    *(unsigned*)(outh + (size_t)row0 * NN + col) = pack2(hx, hy);
                    *(unsigned*)(outl + (size_t)row0 * NN + col) = pack2(lx, ly);
                }
                *(float2*)(outf + (size_t)row0 * NN + col) = make_float2(v0x, v0y);
            }
            if (row1 < M) {
                if (SPLIT_OUT) {
                    bf16 hx, lx, hy, ly;
                    bf16_split(v1x, hx, lx); bf16_split(v1y, hy, ly);
                    *(unsigned*)(outh + (size_t)row1 * NN + col) = pack2(hx, hy);
                    *(unsigned*)(outl + (size_t)row1 * NN + col) = pack2(lx, ly);
                }
                *(float2*)(outf + (size_t)row1 * NN + col) = make_float2(v1x, v1y);
            }
        }
    }
}

// ---------------- final layer + log_softmax ----------------------------------
__global__ void final_kernel(const float* __restrict__ agg,
                             const float* __restrict__ h,
                             const float* __restrict__ Wl,
                             const float* __restrict__ Wr,
                             const float* __restrict__ b,
                             float* __restrict__ out) {
    __shared__ float sWl[H2 * C_OUT], sWr[H2 * C_OUT], sb[C_OUT];
    for (int i = threadIdx.x; i < H2 * C_OUT; i += blockDim.x) {
        sWl[i] = Wl[i];
        sWr[i] = Wr[i];
    }
    if (threadIdx.x < C_OUT) sb[threadIdx.x] = b[threadIdx.x];
    __syncthreads();

    int n = blockIdx.x * blockDim.x + threadIdx.x;
    if (n >= N_NODES) return;

    float logit[C_OUT];
#pragma unroll
    for (int j = 0; j < C_OUT; j++) logit[j] = sb[j];

    const float* ar = agg + (size_t)n * H2;
    const float* hr = h   + (size_t)n * H2;
#pragma unroll 5
    for (int k = 0; k < H2; k++) {
        float a  = ar[k];
        float hh = hr[k];
#pragma unroll
        for (int j = 0; j < C_OUT; j++)
            logit[j] += a * sWl[k * C_OUT + j] + hh * sWr[k * C_OUT + j];
    }

    float mx = logit[0];
#pragma unroll
    for (int j = 1; j < C_OUT; j++) mx = fmaxf(mx, logit[j]);
    float s = 0.0f;
#pragma unroll
    for (int j = 0; j < C_OUT; j++) s += expf(logit[j] - mx);
    float lse = mx + logf(s);
#pragma unroll
    for (int j = 0; j < C_OUT; j++) out[(size_t)n * C_OUT + j] = logit[j] - lse;
}

// ---------------- launch ------------------------------------------------------
extern "C" void kernel_launch(void* const* d_in, const int* in_sizes, int n_in,
                              void* d_out, int out_size) {
    const float* x    = (const float*)d_in[0];
    const int*   ei   = (const int*)d_in[1];
    const float* W_l1 = (const float*)d_in[2];
    const float* b1   = (const float*)d_in[3];
    const float* W_r1 = (const float*)d_in[4];
    const float* W_l2 = (const float*)d_in[5];
    const float* b2   = (const float*)d_in[6];
    const float* W_r2 = (const float*)d_in[7];
    const float* W_l3 = (const float*)d_in[8];
    const float* b3   = (const float*)d_in[9];
    const float* W_r3 = (const float*)d_in[10];
    float* out = (float*)d_out;

    const int* src = ei;
    const int* dst = ei + N_EDGES;

    bf16 *xh, *xl, *a1h, *a1l, *h1h, *h1l, *a2h, *a2l;
    bf16 *w1lh, *w1ll, *w1rh, *w1rl, *w2lh, *w2ll, *w2rh, *w2rl;
    float *h1f, *h2, *agg3;
    cudaGetSymbolAddress((void**)&xh,  g_xh);
    cudaGetSymbolAddress((void**)&xl,  g_xl);
    cudaGetSymbolAddress((void**)&a1h, g_a1h);
    cudaGetSymbolAddress((void**)&a1l, g_a1l);
    cudaGetSymbolAddress((void**)&h1f, g_h1f);
    cudaGetSymbolAddress((void**)&h1h, g_h1h);
    cudaGetSymbolAddress((void**)&h1l, g_h1l);
    cudaGetSymbolAddress((void**)&a2h, g_a2h);
    cudaGetSymbolAddress((void**)&a2l, g_a2l);
    cudaGetSymbolAddress((void**)&h2,  g_h2);
    cudaGetSymbolAddress((void**)&agg3, g_agg3);
    cudaGetSymbolAddress((void**)&w1lh, g_w1lh);
    cudaGetSymbolAddress((void**)&w1ll, g_w1ll);
    cudaGetSymbolAddress((void**)&w1rh, g_w1rh);
    cudaGetSymbolAddress((void**)&w1rl, g_w1rl);
    cudaGetSymbolAddress((void**)&w2lh, g_w2lh);
    cudaGetSymbolAddress((void**)&w2ll, g_w2ll);
    cudaGetSymbolAddress((void**)&w2rh, g_w2rh);
    cudaGetSymbolAddress((void**)&w2rl, g_w2rl);

    const int SMEM1 = (128 + 128) * 24 * 2 * 2 * 3;   // 73728 B
    const int SMEM2 = (128 + 64) * 24 * 2 * 2 * 3;    // 55296 B
    cudaFuncSetAttribute(gemm_cp<2, 8, true>,
                         cudaFuncAttributeMaxDynamicSharedMemorySize, SMEM1);
    cudaFuncSetAttribute(gemm_cp<2, 4, false>,
                         cudaFuncAttributeMaxDynamicSharedMemorySize, SMEM2);

    zero_cnt_kernel<<<(N_NODES + 255) / 256, 256>>>();
    bucket_build_kernel<<<(N_EDGES + 255) / 256, 256>>>(src, dst);
    split_x_kernel<<<(N_NODES * F_IN / 4 + 255) / 256, 256>>>(x, xh, xl);
    split_wt_kernel<<<(F_IN * H1 + 255) / 256, 256>>>(W_l1, w1lh, w1ll, F_IN, H1);
    split_wt_kernel<<<(F_IN * H1 + 255) / 256, 256>>>(W_r1, w1rh, w1rl, F_IN, H1);
    split_wt_kernel<<<(H1 * H2 + 255) / 256, 256>>>(W_l2, w2lh, w2ll, H1, H2);
    split_wt_kernel<<<(H1 * H2 + 255) / 256, 256>>>(W_r2, w2rh, w2rl, H1, H2);

    const int aggBlocks = (N_NODES * 32 + 255) / 256;

    // layer 1
    agg_split_kernel<F_IN><<<aggBlocks, 256>>>(x, a1h, a1l);
    {
        dim3 grid((H1 + 127) / 128, (N_NODES + 127) / 128);
        gemm_cp<2, 8, true><<<grid, 256, SMEM1>>>(
            a1h, a1l, xh, xl, w1lh, w1ll, w1rh, w1rl, b1,
            h1f, h1h, h1l, N_NODES, F_IN, H1);
    }

    // layer 2
    agg_split_kernel<H1><<<aggBlocks, 256>>>(h1f, a2h, a2l);
    {
        dim3 grid((H2 + 63) / 64, (N_NODES + 127) / 128);
        gemm_cp<2, 4, false><<<grid, 256, SMEM2>>>(
            a2h, a2l, h1h, h1l, w2lh, w2ll, w2rh, w2rl, b2,
            h2, nullptr, nullptr, N_NODES, H1, H2);
    }

    // layer 3 + log_softmax
    agg_kernel<H2><<<aggBlocks, 256>>>(h2, agg3);
    final_kernel<<<(N_NODES + 255) / 256, 256>>>(agg3, h2, W_l3, W_r3, b3, out);
}

// round 10
// speedup vs baseline: 1.0338x; 1.0338x over previous
#include <cuda_runtime.h>
#include <cuda_bf16.h>
#include <math.h>

#define N_NODES 100000
#define N_EDGES 1600000
#define F_IN   128
#define H1     200
#define H2     50
#define C_OUT  10
#define MAXDEG 128

typedef __nv_bfloat16 bf16;

// ---------------- scratch -----------------------------------------------------
__device__ int   g_cnt[N_NODES];
__device__ int   g_bucket[(size_t)N_NODES * MAXDEG];
__device__ bf16  g_xh  [(size_t)N_NODES * F_IN];
__device__ bf16  g_xl  [(size_t)N_NODES * F_IN];
__device__ bf16  g_a1h [(size_t)N_NODES * F_IN];
__device__ bf16  g_a1l [(size_t)N_NODES * F_IN];
__device__ float g_h1f [(size_t)N_NODES * H1];
__device__ bf16  g_h1h [(size_t)N_NODES * H1];
__device__ bf16  g_h1l [(size_t)N_NODES * H1];
__device__ bf16  g_a2h [(size_t)N_NODES * H1];
__device__ bf16  g_a2l [(size_t)N_NODES * H1];
__device__ float g_h2  [(size_t)N_NODES * H2];
__device__ float g_agg3[(size_t)N_NODES * H2];
// transposed, split weights: [NN, K]
__device__ bf16  g_w1lh[(size_t)H1 * F_IN], g_w1ll[(size_t)H1 * F_IN];
__device__ bf16  g_w1rh[(size_t)H1 * F_IN], g_w1rl[(size_t)H1 * F_IN];
__device__ bf16  g_w2lh[(size_t)H2 * H1],   g_w2ll[(size_t)H2 * H1];
__device__ bf16  g_w2rh[(size_t)H2 * H1],   g_w2rl[(size_t)H2 * H1];

__device__ __forceinline__ void bf16_split(float x, bf16& h, bf16& l) {
    h = __float2bfloat16(x);
    l = __float2bfloat16(x - __bfloat162float(h));
}

__device__ __forceinline__ unsigned pack2(bf16 a, bf16 b) {
    __nv_bfloat162 p = __halves2bfloat162(a, b);
    return *reinterpret_cast<unsigned*>(&p);
}

// cp.async 16B with zero-fill when !ok
__device__ __forceinline__ void cp16(void* dst, const void* src, bool ok) {
    unsigned d = (unsigned)__cvta_generic_to_shared(dst);
    int ss = ok ? 16 : 0;
    asm volatile("cp.async.ca.shared.global [%0], [%1], 16, %2;"
                 :: "r"(d), "l"(src), "r"(ss));
}
__device__ __forceinline__ void cp_commit() {
    asm volatile("cp.async.commit_group;");
}
__device__ __forceinline__ void cp_wait1() {
    asm volatile("cp.async.wait_group 1;");
}

#define LDSM_X4(r0, r1, r2, r3, addr)                                         \
    asm volatile("ldmatrix.sync.aligned.m8n8.x4.shared.b16 {%0,%1,%2,%3}, [%4];" \
                 : "=r"(r0), "=r"(r1), "=r"(r2), "=r"(r3) : "r"(addr))

__device__ __forceinline__ unsigned sptr(const void* p) {
    return (unsigned)__cvta_generic_to_shared(p);
}

// ---------------- fused prep: zero cnt + split x + split/transpose weights ---
__device__ __forceinline__ void split_wt_elem(const float* W, bf16* th,
                                              bf16* tl, int K, int NN, int j) {
    int n = j / K, k = j - n * K;
    bf16 h, l;
    bf16_split(W[(size_t)k * NN + n], h, l);
    th[j] = h;
    tl[j] = l;
}

__global__ void prep_kernel(const float* __restrict__ x,
                            const float* __restrict__ Wl1,
                            const float* __restrict__ Wr1,
                            const float* __restrict__ Wl2,
                            const float* __restrict__ Wr2) {
    int i = blockIdx.x * blockDim.x + threadIdx.x;
    if (i < N_NODES) g_cnt[i] = 0;
    if (i < N_NODES * F_IN / 4) {
        float4 v = ((const float4*)x)[i];
        bf16 h[4], l[4];
        bf16_split(v.x, h[0], l[0]);
        bf16_split(v.y, h[1], l[1]);
        bf16_split(v.z, h[2], l[2]);
        bf16_split(v.w, h[3], l[3]);
        uint2 uh, ul;
        uh.x = pack2(h[0], h[1]); uh.y = pack2(h[2], h[3]);
        ul.x = pack2(l[0], l[1]); ul.y = pack2(l[2], l[3]);
        *(uint2*)(g_xh + (size_t)i * 4) = uh;
        *(uint2*)(g_xl + (size_t)i * 4) = ul;
    }
    if (i < H1 * F_IN) {
        split_wt_elem(Wl1, g_w1lh, g_w1ll, F_IN, H1, i);
        split_wt_elem(Wr1, g_w1rh, g_w1rl, F_IN, H1, i);
    }
    if (i < H2 * H1) {
        split_wt_elem(Wl2, g_w2lh, g_w2ll, H1, H2, i);
        split_wt_elem(Wr2, g_w2rh, g_w2rl, H1, H2, i);
    }
}

// ---------------- bucket build ------------------------------------------------
__global__ void bucket_build_kernel(const int* __restrict__ src,
                                    const int* __restrict__ dst) {
    int e = blockIdx.x * blockDim.x + threadIdx.x;
    if (e >= N_EDGES) return;
    int d = dst[e];
    int p = atomicAdd(&g_cnt[d], 1);
    if (p < MAXDEG) g_bucket[(size_t)d * MAXDEG + p] = src[e];
}

__device__ __forceinline__ void fmax4(float4& m, float4 v) {
    m.x = fmaxf(m.x, v.x);
    m.y = fmaxf(m.y, v.y);
    m.z = fmaxf(m.z, v.z);
    m.w = fmaxf(m.w, v.w);
}
__device__ __forceinline__ void fmax2(float2& m, float2 v) {
    m.x = fmaxf(m.x, v.x);
    m.y = fmaxf(m.y, v.y);
}

// ---------------- aggregation: fp32 gather, split-bf16 output ----------------
template <int F>
__global__ void agg_split_kernel(const float* __restrict__ x,
                                 bf16* __restrict__ oh, bf16* __restrict__ ol) {
    constexpr int C4 = F / 4;
    constexpr int RV = (C4 + 31) / 32;

    int gwarp = (blockIdx.x * blockDim.x + threadIdx.x) >> 5;
    int lane  = threadIdx.x & 31;
    if (gwarp >= N_NODES) return;

    int c = g_cnt[gwarp];
    if (c > MAXDEG) c = MAXDEG;

    float4 m[RV];
#pragma unroll
    for (int r = 0; r < RV; r++)
        m[r] = make_float4(-INFINITY, -INFINITY, -INFINITY, -INFINITY);

    const int* bk = g_bucket + (size_t)gwarp * MAXDEG;
    int i = 0;
    for (; i + 3 < c; i += 4) {
        int s0 = bk[i], s1 = bk[i + 1], s2 = bk[i + 2], s3 = bk[i + 3];
        const float4* p0 = (const float4*)(x + (size_t)s0 * F);
        const float4* p1 = (const float4*)(x + (size_t)s1 * F);
        const float4* p2 = (const float4*)(x + (size_t)s2 * F);
        const float4* p3 = (const float4*)(x + (size_t)s3 * F);
#pragma unroll
        for (int r = 0; r < RV; r++) {
            int ch = lane + r * 32;
            if (ch < C4) {
                float4 v0 = p0[ch], v1 = p1[ch], v2 = p2[ch], v3 = p3[ch];
                fmax4(v0, v1); fmax4(v2, v3);
                fmax4(v0, v2);
                fmax4(m[r], v0);
            }
        }
    }
    for (; i < c; i++) {
        const float4* p0 = (const float4*)(x + (size_t)bk[i] * F);
#pragma unroll
        for (int r = 0; r < RV; r++) {
            int ch = lane + r * 32;
            if (ch < C4) fmax4(m[r], p0[ch]);
        }
    }

#pragma unroll
    for (int r = 0; r < RV; r++) {
        int ch = lane + r * 32;
        if (ch < C4) {
            float v[4] = {m[r].x, m[r].y, m[r].z, m[r].w};
            bf16 hh[4], ll[4];
#pragma unroll
            for (int q = 0; q < 4; q++) {
                float vv = (c == 0) ? 0.f : v[q];
                bf16_split(vv, hh[q], ll[q]);
            }
            uint2 uh, ul;
            uh.x = pack2(hh[0], hh[1]); uh.y = pack2(hh[2], hh[3]);
            ul.x = pack2(ll[0], ll[1]); ul.y = pack2(ll[2], ll[3]);
            *(uint2*)(oh + (size_t)gwarp * F + ch * 4) = uh;
            *(uint2*)(ol + (size_t)gwarp * F + ch * 4) = ul;
        }
    }
}

// ---------------- fp32 aggregation (layer 3, H2=50) --------------------------
template <int F>
__global__ void agg_kernel(const float* __restrict__ x, float* __restrict__ agg) {
    constexpr int C2 = F / 2;
    constexpr int RV = (C2 + 31) / 32;

    int gwarp = (blockIdx.x * blockDim.x + threadIdx.x) >> 5;
    int lane  = threadIdx.x & 31;
    if (gwarp >= N_NODES) return;

    int c = g_cnt[gwarp];
    if (c > MAXDEG) c = MAXDEG;

    float2 m[RV];
#pragma unroll
    for (int r = 0; r < RV; r++) { m[r].x = -INFINITY; m[r].y = -INFINITY; }

    const int* bk = g_bucket + (size_t)gwarp * MAXDEG;
    int i = 0;
    for (; i + 3 < c; i += 4) {
        int s0 = bk[i], s1 = bk[i + 1], s2 = bk[i + 2], s3 = bk[i + 3];
        const float2* p0 = (const float2*)(x + (size_t)s0 * F);
        const float2* p1 = (const float2*)(x + (size_t)s1 * F);
        const float2* p2 = (const float2*)(x + (size_t)s2 * F);
        const float2* p3 = (const float2*)(x + (size_t)s3 * F);
#pragma unroll
        for (int r = 0; r < RV; r++) {
            int ch = lane + r * 32;
            if (ch < C2) {
                float2 v0 = p0[ch], v1 = p1[ch], v2 = p2[ch], v3 = p3[ch];
                fmax2(v0, v1); fmax2(v2, v3);
                fmax2(v0, v2);
                fmax2(m[r], v0);
            }
        }
    }
    for (; i < c; i++) {
        const float2* p0 = (const float2*)(x + (size_t)bk[i] * F);
#pragma unroll
        for (int r = 0; r < RV; r++) {
            int ch = lane + r * 32;
            if (ch < C2) fmax2(m[r], p0[ch]);
        }
    }

    float2* out = (float2*)(agg + (size_t)gwarp * F);
#pragma unroll
    for (int r = 0; r < RV; r++) {
        int ch = lane + r * 32;
        if (ch < C2) out[ch] = (c == 0) ? make_float2(0.f, 0.f) : m[r];
    }
}

// ---------------- all-bf16 tensor-core dual GEMM, cp.async + ldmatrix --------
#define MMA16816(d, a, b0, b1)                                                \
    asm volatile(                                                             \
        "mma.sync.aligned.m16n8k16.row.col.f32.bf16.bf16.f32 "                \
        "{%0,%1,%2,%3}, {%4,%5,%6,%7}, {%8,%9}, {%0,%1,%2,%3};"               \
        : "+f"(d[0]), "+f"(d[1]), "+f"(d[2]), "+f"(d[3])                      \
        : "r"(a[0]), "r"(a[1]), "r"(a[2]), "r"(a[3]), "r"(b0), "r"(b1))

// All operands pre-split bf16. A [M,K] row-major hi/lo; B (=W^T) [NN,K]
// row-major hi/lo. BM=128 (WM=4), BN=WN*NT*8. 3-stage cp.async; fragment
// loads via ldmatrix.x4 (LDSTR=24 rows -> conflict-free LDSM phases).
template <int WN, int NT, bool SPLIT_OUT>
__global__ __launch_bounds__(256, 2)
void gemm_cp(const bf16* __restrict__ Ah1, const bf16* __restrict__ Al1,
             const bf16* __restrict__ Ah2, const bf16* __restrict__ Al2,
             const bf16* __restrict__ Bh1, const bf16* __restrict__ Bl1,
             const bf16* __restrict__ Bh2, const bf16* __restrict__ Bl2,
             const float* __restrict__ bias,
             float* __restrict__ outf,
             bf16* __restrict__ outh, bf16* __restrict__ outl,
             int M, int K, int NN) {
    constexpr int WM = 4;
    constexpr int BM = 128;
    constexpr int BN = WN * NT * 8;
    constexpr int LDSTR = 24;
    constexpr int ST = 3;
    static_assert(NT % 2 == 0, "NT must be even for paired ldmatrix");

    extern __shared__ __align__(16) char smem_raw[];
    bf16* Ash = (bf16*)smem_raw;
    bf16* Asl = Ash + ST * BM * LDSTR;
    bf16* Bsh = Asl + ST * BM * LDSTR;
    bf16* Bsl = Bsh + ST * BN * LDSTR;

    int tid = threadIdx.x;
    int lane = tid & 31;
    int wid = tid >> 5;
    int wm = wid % WM;
    int wn = wid / WM;
    int g  = lane >> 2;
    int tg = lane & 3;
    int lr = lane & 15;           // ldmatrix row-in-group
    int lc = (lane >> 4) * 8;     // ldmatrix k-half

    int rowBase = blockIdx.y * BM;
    int colBase = blockIdx.x * BN;

    int npt  = (K + 15) >> 4;
    int totT = 2 * npt;

    const int r_  = tid >> 1;
    const int kh_ = (tid & 1) * 8;
    const int aRow = rowBase + r_;
    const int bn_ = tid >> 1;
    const int gN  = colBase + bn_;

    float acc[2][NT][4];
#pragma unroll
    for (int mt = 0; mt < 2; mt++)
#pragma unroll
        for (int nt = 0; nt < NT; nt++)
#pragma unroll
            for (int q = 0; q < 4; q++) acc[mt][nt][q] = 0.f;

    auto issue = [&](int t, int s) {
        const bf16 *Ah, *Al, *Bh, *Bl; int ko;
        if (t < npt) { Ah = Ah1; Al = Al1; Bh = Bh1; Bl = Bl1; ko = t << 4; }
        else { Ah = Ah2; Al = Al2; Bh = Bh2; Bl = Bl2; ko = (t - npt) << 4; }
        int gk = ko + kh_;
        bool okA = (aRow < M) && (gk + 8 <= K);
        const bf16* sah = okA ? (Ah + (size_t)aRow * K + gk) : Ah;
        const bf16* sal = okA ? (Al + (size_t)aRow * K + gk) : Al;
        cp16(&Ash[s * BM * LDSTR + r_ * LDSTR + kh_], sah, okA);
        cp16(&Asl[s * BM * LDSTR + r_ * LDSTR + kh_], sal, okA);
        if (bn_ < BN) {
            bool okB = (gN < NN) && (gk + 8 <= K);
            const bf16* sbh = okB ? (Bh + (size_t)gN * K + gk) : Bh;
            const bf16* sbl = okB ? (Bl + (size_t)gN * K + gk) : Bl;
            cp16(&Bsh[s * BN * LDSTR + bn_ * LDSTR + kh_], sbh, okB);
            cp16(&Bsl[s * BN * LDSTR + bn_ * LDSTR + kh_], sbl, okB);
        }
    };

    auto compute = [&](int s) {
        const bf16* As_h = Ash + s * BM * LDSTR;
        const bf16* As_l = Asl + s * BM * LDSTR;
        const bf16* Bs_h = Bsh + s * BN * LDSTR;
        const bf16* Bs_l = Bsl + s * BN * LDSTR;

        unsigned afh[2][4], afl[2][4];
#pragma unroll
        for (int mt = 0; mt < 2; mt++) {
            int r0 = wm * 32 + mt * 16 + lr;
            LDSM_X4(afh[mt][0], afh[mt][1], afh[mt][2], afh[mt][3],
                    sptr(&As_h[r0 * LDSTR + lc]));
            LDSM_X4(afl[mt][0], afl[mt][1], afl[mt][2], afl[mt][3],
                    sptr(&As_l[r0 * LDSTR + lc]));
        }

#pragma unroll
        for (int p = 0; p < NT / 2; p++) {
            int rowb = (wn * NT + 2 * p) * 8 + lr;
            unsigned bh0, bh1, bh2, bh3, bl0, bl1, bl2, bl3;
            LDSM_X4(bh0, bh1, bh2, bh3, sptr(&Bs_h[rowb * LDSTR + lc]));
            LDSM_X4(bl0, bl1, bl2, bl3, sptr(&Bs_l[rowb * LDSTR + lc]));
#pragma unroll
            for (int mt = 0; mt < 2; mt++) {
                MMA16816(acc[mt][2 * p],     afh[mt], bh0, bh2);
                MMA16816(acc[mt][2 * p],     afh[mt], bl0, bl2);
                MMA16816(acc[mt][2 * p],     afl[mt], bh0, bh2);
                MMA16816(acc[mt][2 * p + 1], afh[mt], bh1, bh3);
                MMA16816(acc[mt][2 * p + 1], afh[mt], bl1, bl3);
                MMA16816(acc[mt][2 * p + 1], afl[mt], bh1, bh3);
            }
        }
    };

    issue(0, 0); cp_commit();
    if (totT > 1) issue(1, 1);
    cp_commit();

    for (int t = 0; t < totT; t++) {
        cp_wait1();
        __syncthreads();
        if (t + 2 < totT) issue(t + 2, (t + 2) % ST);
        cp_commit();
        compute(t % ST);
    }

    // ---- epilogue ----
#pragma unroll
    for (int mt = 0; mt < 2; mt++) {
#pragma unroll
        for (int nt = 0; nt < NT; nt++) {
            int col = colBase + (wn * NT + nt) * 8 + 2 * tg;
            if (col >= NN) continue;
            float2 bv = *(const float2*)(bias + col);
            int row0 = rowBase + wm * 32 + mt * 16 + g;
            int row1 = row0 + 8;
            float v0x = acc[mt][nt][0] + bv.x, v0y = acc[mt][nt][1] + bv.y;
            float v1x = acc[mt][nt][2] + bv.x, v1y = acc[mt][nt][3] + bv.y;
            if (row0 < M) {
                if (SPLIT_OUT) {
                    bf16 hx, lx, hy, ly;
                    bf16_split(v0x, hx, lx); bf16_split(v0y, hy, ly);
                    *(unsigned*)(outh + (size_t)row0 * NN + col) = pack2(hx, hy);
                    *(unsigned*)(outl + (size_t)row0 * NN + col) = pack2(lx, ly);
                }
                *(float2*)(outf + (size_t)row0 * NN + col) = make_float2(v0x, v0y);
            }
            if (row1 < M) {
                if (SPLIT_OUT) {
                    bf16 hx, lx, hy, ly;
                    bf16_split(v1x, hx, lx); bf16_split(v1y, hy, ly);
                    *(unsigned*)(outh + (size_t)row1 * NN + col) = pack2(hx, hy);
                    *(unsigned*)(outl + (size_t)row1 * NN + col) = pack2(lx, ly);
                }
                *(float2*)(outf + (size_t)row1 * NN + col) = make_float2(v1x, v1y);
            }
        }
    }
}

// ---------------- final layer + log_softmax ----------------------------------
__global__ void final_kernel(const float* __restrict__ agg,
                             const float* __restrict__ h,
                             const float* __restrict__ Wl,
                             const float* __restrict__ Wr,
                             const float* __restrict__ b,
                             float* __restrict__ out) {
    __shared__ float sWl[H2 * C_OUT], sWr[H2 * C_OUT], sb[C_OUT];
    for (int i = threadIdx.x; i < H2 * C_OUT; i += blockDim.x) {
        sWl[i] = Wl[i];
        sWr[i] = Wr[i];
    }
    if (threadIdx.x < C_OUT) sb[threadIdx.x] = b[threadIdx.x];
    __syncthreads();

    int n = blockIdx.x * blockDim.x + threadIdx.x;
    if (n >= N_NODES) return;

    float logit[C_OUT];
#pragma unroll
    for (int j = 0; j < C_OUT; j++) logit[j] = sb[j];

    const float* ar = agg + (size_t)n * H2;
    const float* hr = h   + (size_t)n * H2;
#pragma unroll 5
    for (int k = 0; k < H2; k++) {
        float a  = ar[k];
        float hh = hr[k];
#pragma unroll
        for (int j = 0; j < C_OUT; j++)
            logit[j] += a * sWl[k * C_OUT + j] + hh * sWr[k * C_OUT + j];
    }

    float mx = logit[0];
#pragma unroll
    for (int j = 1; j < C_OUT; j++) mx = fmaxf(mx, logit[j]);
    float s = 0.0f;
#pragma unroll
    for (int j = 0; j < C_OUT; j++) s += expf(logit[j] - mx);
    float lse = mx + logf(s);
#pragma unroll
    for (int j = 0; j < C_OUT; j++) out[(size_t)n * C_OUT + j] = logit[j] - lse;
}

// ---------------- launch ------------------------------------------------------
extern "C" void kernel_launch(void* const* d_in, const int* in_sizes, int n_in,
                              void* d_out, int out_size) {
    const float* x    = (const float*)d_in[0];
    const int*   ei   = (const int*)d_in[1];
    const float* W_l1 = (const float*)d_in[2];
    const float* b1   = (const float*)d_in[3];
    const float* W_r1 = (const float*)d_in[4];
    const float* W_l2 = (const float*)d_in[5];
    const float* b2   = (const float*)d_in[6];
    const float* W_r2 = (const float*)d_in[7];
    const float* W_l3 = (const float*)d_in[8];
    const float* b3   = (const float*)d_in[9];
    const float* W_r3 = (const float*)d_in[10];
    float* out = (float*)d_out;

    const int* src = ei;
    const int* dst = ei + N_EDGES;

    bf16 *xh, *xl, *a1h, *a1l, *h1h, *h1l, *a2h, *a2l;
    bf16 *w1lh, *w1ll, *w1rh, *w1rl, *w2lh, *w2ll, *w2rh, *w2rl;
    float *h1f, *h2, *agg3;
    cudaGetSymbolAddress((void**)&xh,  g_xh);
    cudaGetSymbolAddress((void**)&xl,  g_xl);
    cudaGetSymbolAddress((void**)&a1h, g_a1h);
    cudaGetSymbolAddress((void**)&a1l, g_a1l);
    cudaGetSymbolAddress((void**)&h1f, g_h1f);
    cudaGetSymbolAddress((void**)&h1h, g_h1h);
    cudaGetSymbolAddress((void**)&h1l, g_h1l);
    cudaGetSymbolAddress((void**)&a2h, g_a2h);
    cudaGetSymbolAddress((void**)&a2l, g_a2l);
    cudaGetSymbolAddress((void**)&h2,  g_h2);
    cudaGetSymbolAddress((void**)&agg3, g_agg3);
    cudaGetSymbolAddress((void**)&w1lh, g_w1lh);
    cudaGetSymbolAddress((void**)&w1ll, g_w1ll);
    cudaGetSymbolAddress((void**)&w1rh, g_w1rh);
    cudaGetSymbolAddress((void**)&w1rl, g_w1rl);
    cudaGetSymbolAddress((void**)&w2lh, g_w2lh);
    cudaGetSymbolAddress((void**)&w2ll, g_w2ll);
    cudaGetSymbolAddress((void**)&w2rh, g_w2rh);
    cudaGetSymbolAddress((void**)&w2rl, g_w2rl);

    const int SMEM1 = (128 + 128) * 24 * 2 * 2 * 3;   // 73728 B
    const int SMEM2 = (128 + 64) * 24 * 2 * 2 * 3;    // 55296 B
    cudaFuncSetAttribute(gemm_cp<2, 8, true>,
                         cudaFuncAttributeMaxDynamicSharedMemorySize, SMEM1);
    cudaFuncSetAttribute(gemm_cp<2, 4, false>,
                         cudaFuncAttributeMaxDynamicSharedMemorySize, SMEM2);

    // fused prework: zero cnt + split x + split/transpose all weights
    prep_kernel<<<(N_NODES * F_IN / 4 + 255) / 256, 256>>>(x, W_l1, W_r1,
                                                           W_l2, W_r2);
    bucket_build_kernel<<<(N_EDGES + 255) / 256, 256>>>(src, dst);

    const int aggBlocks = (N_NODES * 32 + 255) / 256;

    // layer 1
    agg_split_kernel<F_IN><<<aggBlocks, 256>>>(x, a1h, a1l);
    {
        dim3 grid((H1 + 127) / 128, (N_NODES + 127) / 128);
        gemm_cp<2, 8, true><<<grid, 256, SMEM1>>>(
            a1h, a1l, xh, xl, w1lh, w1ll, w1rh, w1rl, b1,
            h1f, h1h, h1l, N_NODES, F_IN, H1);
    }

    // layer 2
    agg_split_kernel<H1><<<aggBlocks, 256>>>(h1f, a2h, a2l);
    {
        dim3 grid((H2 + 63) / 64, (N_NODES + 127) / 128);
        gemm_cp<2, 4, false><<<grid, 256, SMEM2>>>(
            a2h, a2l, h1h, h1l, w2lh, w2ll, w2rh, w2rl, b2,
            h2, nullptr, nullptr, N_NODES, H1, H2);
    }

    // layer 3 + log_softmax
    agg_kernel<H2><<<aggBlocks, 256>>>(h2, agg3);
    final_kernel<<<(N_NODES + 255) / 256, 256>>>(agg3, h2, W_l3, W_r3, b3, out);
}

// round 11
// speedup vs baseline: 1.2530x; 1.2120x over previous
#include <cuda_runtime.h>
#include <cuda_fp16.h>
#include <math.h>

#define N_NODES 100000
#define N_EDGES 1600000
#define F_IN   128
#define H1     200
#define H1P    208   // K-padded so fp16 rows are 416B = 16B-aligned
#define H2     50
#define C_OUT  10
#define MAXDEG 128

typedef __half h16;

// ---------------- scratch -----------------------------------------------------
__device__ int   g_cnt[N_NODES];
__device__ int   g_bucket[(size_t)N_NODES * MAXDEG];
__device__ h16   g_xh  [(size_t)N_NODES * F_IN];
__device__ h16   g_a1h [(size_t)N_NODES * F_IN];
__device__ float g_h1f [(size_t)N_NODES * H1];
__device__ h16   g_h1h [(size_t)N_NODES * H1P];
__device__ h16   g_a2h [(size_t)N_NODES * H1P];
__device__ float g_h2  [(size_t)N_NODES * H2];
__device__ float g_agg3[(size_t)N_NODES * H2];
// transposed weights [NN, Kpad]: hi + lo fp16 planes
__device__ h16   g_w1lh[(size_t)H1 * F_IN], g_w1ll[(size_t)H1 * F_IN];
__device__ h16   g_w1rh[(size_t)H1 * F_IN], g_w1rl[(size_t)H1 * F_IN];
__device__ h16   g_w2lh[(size_t)H2 * H1P],  g_w2ll[(size_t)H2 * H1P];
__device__ h16   g_w2rh[(size_t)H2 * H1P],  g_w2rl[(size_t)H2 * H1P];

__device__ __forceinline__ void h16_split(float x, h16& h, h16& l) {
    h = __float2half_rn(x);
    l = __float2half_rn(x - __half2float(h));
}
__device__ __forceinline__ unsigned packh2(h16 a, h16 b) {
    __half2 p = __halves2half2(a, b);
    return *reinterpret_cast<unsigned*>(&p);
}

// cp.async 16B with zero-fill when !ok
__device__ __forceinline__ void cp16(void* dst, const void* src, bool ok) {
    unsigned d = (unsigned)__cvta_generic_to_shared(dst);
    int ss = ok ? 16 : 0;
    asm volatile("cp.async.ca.shared.global [%0], [%1], 16, %2;"
                 :: "r"(d), "l"(src), "r"(ss));
}
__device__ __forceinline__ void cp_commit() {
    asm volatile("cp.async.commit_group;");
}
__device__ __forceinline__ void cp_wait1() {
    asm volatile("cp.async.wait_group 1;");
}

#define LDSM_X4(r0, r1, r2, r3, addr)                                         \
    asm volatile("ldmatrix.sync.aligned.m8n8.x4.shared.b16 {%0,%1,%2,%3}, [%4];" \
                 : "=r"(r0), "=r"(r1), "=r"(r2), "=r"(r3) : "r"(addr))

__device__ __forceinline__ unsigned sptr(const void* p) {
    return (unsigned)__cvta_generic_to_shared(p);
}

// ---------------- fused prep --------------------------------------------------
__global__ void prep_kernel(const float* __restrict__ x,
                            const float* __restrict__ Wl1,
                            const float* __restrict__ Wr1,
                            const float* __restrict__ Wl2,
                            const float* __restrict__ Wr2) {
    int i = blockIdx.x * blockDim.x + threadIdx.x;
    if (i < N_NODES) g_cnt[i] = 0;
    if (i < N_NODES * F_IN / 4) {           // x -> fp16 (single plane)
        float4 v = ((const float4*)x)[i];
        uint2 uo;
        uo.x = packh2(__float2half_rn(v.x), __float2half_rn(v.y));
        uo.y = packh2(__float2half_rn(v.z), __float2half_rn(v.w));
        *(uint2*)(g_xh + (size_t)i * 4) = uo;
    }
    if (i < H1 * F_IN) {                    // W1 l/r -> transposed hi/lo
        int n = i / F_IN, k = i - n * F_IN;
        h16 h, l;
        h16_split(Wl1[(size_t)k * H1 + n], h, l);
        g_w1lh[i] = h; g_w1ll[i] = l;
        h16_split(Wr1[(size_t)k * H1 + n], h, l);
        g_w1rh[i] = h; g_w1rl[i] = l;
    }
    if (i < H2 * H1P) {                     // W2 l/r -> transposed hi/lo, padded
        int n = i / H1P, k = i - n * H1P;
        float vl = (k < H1) ? Wl2[(size_t)k * H2 + n] : 0.f;
        float vr = (k < H1) ? Wr2[(size_t)k * H2 + n] : 0.f;
        h16 h, l;
        h16_split(vl, h, l);
        g_w2lh[i] = h; g_w2ll[i] = l;
        h16_split(vr, h, l);
        g_w2rh[i] = h; g_w2rl[i] = l;
    }
    if (i < N_NODES * 8) {                  // zero K-pads of h1h / a2h
        int node = i >> 3, kk = H1 + (i & 7);
        g_h1h[(size_t)node * H1P + kk] = __float2half_rn(0.f);
        g_a2h[(size_t)node * H1P + kk] = __float2half_rn(0.f);
    }
}

// ---------------- bucket build ------------------------------------------------
__global__ void bucket_build_kernel(const int* __restrict__ src,
                                    const int* __restrict__ dst) {
    int e = blockIdx.x * blockDim.x + threadIdx.x;
    if (e >= N_EDGES) return;
    int d = dst[e];
    int p = atomicAdd(&g_cnt[d], 1);
    if (p < MAXDEG) g_bucket[(size_t)d * MAXDEG + p] = src[e];
}

__device__ __forceinline__ void fmax4(float4& m, float4 v) {
    m.x = fmaxf(m.x, v.x);
    m.y = fmaxf(m.y, v.y);
    m.z = fmaxf(m.z, v.z);
    m.w = fmaxf(m.w, v.w);
}
__device__ __forceinline__ void fmax2(float2& m, float2 v) {
    m.x = fmaxf(m.x, v.x);
    m.y = fmaxf(m.y, v.y);
}

// ---------------- aggregation: fp32 gather, fp16 output ----------------------
template <int F, int OSTR>
__global__ void agg_split_kernel(const float* __restrict__ x,
                                 h16* __restrict__ o) {
    constexpr int C4 = F / 4;
    constexpr int RV = (C4 + 31) / 32;

    int gwarp = (blockIdx.x * blockDim.x + threadIdx.x) >> 5;
    int lane  = threadIdx.x & 31;
    if (gwarp >= N_NODES) return;

    int c = g_cnt[gwarp];
    if (c > MAXDEG) c = MAXDEG;

    float4 m[RV];
#pragma unroll
    for (int r = 0; r < RV; r++)
        m[r] = make_float4(-INFINITY, -INFINITY, -INFINITY, -INFINITY);

    const int* bk = g_bucket + (size_t)gwarp * MAXDEG;
    int i = 0;
    for (; i + 3 < c; i += 4) {
        int s0 = bk[i], s1 = bk[i + 1], s2 = bk[i + 2], s3 = bk[i + 3];
        const float4* p0 = (const float4*)(x + (size_t)s0 * F);
        const float4* p1 = (const float4*)(x + (size_t)s1 * F);
        const float4* p2 = (const float4*)(x + (size_t)s2 * F);
        const float4* p3 = (const float4*)(x + (size_t)s3 * F);
#pragma unroll
        for (int r = 0; r < RV; r++) {
            int ch = lane + r * 32;
            if (ch < C4) {
                float4 v0 = p0[ch], v1 = p1[ch], v2 = p2[ch], v3 = p3[ch];
                fmax4(v0, v1); fmax4(v2, v3);
                fmax4(v0, v2);
                fmax4(m[r], v0);
            }
        }
    }
    for (; i < c; i++) {
        const float4* p0 = (const float4*)(x + (size_t)bk[i] * F);
#pragma unroll
        for (int r = 0; r < RV; r++) {
            int ch = lane + r * 32;
            if (ch < C4) fmax4(m[r], p0[ch]);
        }
    }

#pragma unroll
    for (int r = 0; r < RV; r++) {
        int ch = lane + r * 32;
        if (ch < C4) {
            float v[4] = {m[r].x, m[r].y, m[r].z, m[r].w};
            h16 hh[4];
#pragma unroll
            for (int q = 0; q < 4; q++)
                hh[q] = __float2half_rn((c == 0) ? 0.f : v[q]);
            uint2 uo;
            uo.x = packh2(hh[0], hh[1]);
            uo.y = packh2(hh[2], hh[3]);
            *(uint2*)(o + (size_t)gwarp * OSTR + ch * 4) = uo;
        }
    }
}

// ---------------- fp32 aggregation (layer 3, H2=50) --------------------------
template <int F>
__global__ void agg_kernel(const float* __restrict__ x, float* __restrict__ agg) {
    constexpr int C2 = F / 2;
    constexpr int RV = (C2 + 31) / 32;

    int gwarp = (blockIdx.x * blockDim.x + threadIdx.x) >> 5;
    int lane  = threadIdx.x & 31;
    if (gwarp >= N_NODES) return;

    int c = g_cnt[gwarp];
    if (c > MAXDEG) c = MAXDEG;

    float2 m[RV];
#pragma unroll
    for (int r = 0; r < RV; r++) { m[r].x = -INFINITY; m[r].y = -INFINITY; }

    const int* bk = g_bucket + (size_t)gwarp * MAXDEG;
    int i = 0;
    for (; i + 3 < c; i += 4) {
        int s0 = bk[i], s1 = bk[i + 1], s2 = bk[i + 2], s3 = bk[i + 3];
        const float2* p0 = (const float2*)(x + (size_t)s0 * F);
        const float2* p1 = (const float2*)(x + (size_t)s1 * F);
        const float2* p2 = (const float2*)(x + (size_t)s2 * F);
        const float2* p3 = (const float2*)(x + (size_t)s3 * F);
#pragma unroll
        for (int r = 0; r < RV; r++) {
            int ch = lane + r * 32;
            if (ch < C2) {
                float2 v0 = p0[ch], v1 = p1[ch], v2 = p2[ch], v3 = p3[ch];
                fmax2(v0, v1); fmax2(v2, v3);
                fmax2(v0, v2);
                fmax2(m[r], v0);
            }
        }
    }
    for (; i < c; i++) {
        const float2* p0 = (const float2*)(x + (size_t)bk[i] * F);
#pragma unroll
        for (int r = 0; r < RV; r++) {
            int ch = lane + r * 32;
            if (ch < C2) fmax2(m[r], p0[ch]);
        }
    }

    float2* out = (float2*)(agg + (size_t)gwarp * F);
#pragma unroll
    for (int r = 0; r < RV; r++) {
        int ch = lane + r * 32;
        if (ch < C2) out[ch] = (c == 0) ? make_float2(0.f, 0.f) : m[r];
    }
}

// ---------------- fp16 2-term tensor-core dual GEMM --------------------------
// out = A1@W1 + A2@W2 + bias, where A is single-plane fp16 and B (=W^T) is
// fp16 hi+lo: product ~= A*(Bh+Bl) -> 2 MMAs per logical product.
#define MMAF16(d, a, b0, b1)                                                  \
    asm volatile(                                                             \
        "mma.sync.aligned.m16n8k16.row.col.f32.f16.f16.f32 "                  \
        "{%0,%1,%2,%3}, {%4,%5,%6,%7}, {%8,%9}, {%0,%1,%2,%3};"               \
        : "+f"(d[0]), "+f"(d[1]), "+f"(d[2]), "+f"(d[3])                      \
        : "r"(a[0]), "r"(a[1]), "r"(a[2]), "r"(a[3]), "r"(b0), "r"(b1))

template <int WN, int NT, bool SPLIT_OUT>
__global__ __launch_bounds__(256, 2)
void gemm_cp(const h16* __restrict__ A1, const h16* __restrict__ A2,
             const h16* __restrict__ Bh1, const h16* __restrict__ Bl1,
             const h16* __restrict__ Bh2, const h16* __restrict__ Bl2,
             const float* __restrict__ bias,
             float* __restrict__ outf, h16* __restrict__ outh,
             int M, int K, int NN, int ostride) {
    constexpr int WM = 4;
    constexpr int BM = 128;
    constexpr int BN = WN * NT * 8;
    constexpr int LDSTR = 24;
    constexpr int ST = 3;
    static_assert(NT % 2 == 0, "NT must be even");

    extern __shared__ __align__(16) char smem_raw[];
    h16* Ash = (h16*)smem_raw;                  // ST * BM * LDSTR
    h16* Bsh = Ash + ST * BM * LDSTR;           // ST * BN * LDSTR
    h16* Bsl = Bsh + ST * BN * LDSTR;

    int tid = threadIdx.x;
    int lane = tid & 31;
    int wid = tid >> 5;
    int wm = wid % WM;
    int wn = wid / WM;
    int g  = lane >> 2;
    int tg = lane & 3;
    int lr = lane & 15;
    int lc = (lane >> 4) * 8;

    int rowBase = blockIdx.y * BM;
    int colBase = blockIdx.x * BN;

    int npt  = (K + 15) >> 4;
    int totT = 2 * npt;

    const int r_  = tid >> 1;
    const int kh_ = (tid & 1) * 8;
    const int aRow = rowBase + r_;
    const int bn_ = tid >> 1;
    const int gN  = colBase + bn_;

    float acc[2][NT][4];
#pragma unroll
    for (int mt = 0; mt < 2; mt++)
#pragma unroll
        for (int nt = 0; nt < NT; nt++)
#pragma unroll
            for (int q = 0; q < 4; q++) acc[mt][nt][q] = 0.f;

    auto issue = [&](int t, int s) {
        const h16 *A, *Bh, *Bl; int ko;
        if (t < npt) { A = A1; Bh = Bh1; Bl = Bl1; ko = t << 4; }
        else         { A = A2; Bh = Bh2; Bl = Bl2; ko = (t - npt) << 4; }
        int gk = ko + kh_;
        bool okA = (aRow < M) && (gk + 8 <= K);
        cp16(&Ash[s * BM * LDSTR + r_ * LDSTR + kh_],
             okA ? (A + (size_t)aRow * K + gk) : A, okA);
        if (bn_ < BN) {
            bool okB = (gN < NN) && (gk + 8 <= K);
            cp16(&Bsh[s * BN * LDSTR + bn_ * LDSTR + kh_],
                 okB ? (Bh + (size_t)gN * K + gk) : Bh, okB);
            cp16(&Bsl[s * BN * LDSTR + bn_ * LDSTR + kh_],
                 okB ? (Bl + (size_t)gN * K + gk) : Bl, okB);
        }
    };

    auto compute = [&](int s) {
        const h16* As = Ash + s * BM * LDSTR;
        const h16* Bs_h = Bsh + s * BN * LDSTR;
        const h16* Bs_l = Bsl + s * BN * LDSTR;

        unsigned af[2][4];
#pragma unroll
        for (int mt = 0; mt < 2; mt++) {
            int r0 = wm * 32 + mt * 16 + lr;
            LDSM_X4(af[mt][0], af[mt][1], af[mt][2], af[mt][3],
                    sptr(&As[r0 * LDSTR + lc]));
        }

#pragma unroll
        for (int p = 0; p < NT / 2; p++) {
            int rowb = (wn * NT + 2 * p) * 8 + lr;
            unsigned bh0, bh1, bh2, bh3, bl0, bl1, bl2, bl3;
            LDSM_X4(bh0, bh1, bh2, bh3, sptr(&Bs_h[rowb * LDSTR + lc]));
            LDSM_X4(bl0, bl1, bl2, bl3, sptr(&Bs_l[rowb * LDSTR + lc]));
            // hi step: 4 independent MMAs
            MMAF16(acc[0][2 * p],     af[0], bh0, bh2);
            MMAF16(acc[1][2 * p],     af[1], bh0, bh2);
            MMAF16(acc[0][2 * p + 1], af[0], bh1, bh3);
            MMAF16(acc[1][2 * p + 1], af[1], bh1, bh3);
            // lo step: 4 independent MMAs
            MMAF16(acc[0][2 * p],     af[0], bl0, bl2);
            MMAF16(acc[1][2 * p],     af[1], bl0, bl2);
            MMAF16(acc[0][2 * p + 1], af[0], bl1, bl3);
            MMAF16(acc[1][2 * p + 1], af[1], bl1, bl3);
        }
    };

    issue(0, 0); cp_commit();
    if (totT > 1) issue(1, 1);
    cp_commit();

    for (int t = 0; t < totT; t++) {
        cp_wait1();
        __syncthreads();
        if (t + 2 < totT) issue(t + 2, (t + 2) % ST);
        cp_commit();
        compute(t % ST);
    }

    // ---- epilogue ----
#pragma unroll
    for (int mt = 0; mt < 2; mt++) {
#pragma unroll
        for (int nt = 0; nt < NT; nt++) {
            int col = colBase + (wn * NT + nt) * 8 + 2 * tg;
            if (col >= NN) continue;
            float2 bv = *(const float2*)(bias + col);
            int row0 = rowBase + wm * 32 + mt * 16 + g;
            int row1 = row0 + 8;
            float v0x = acc[mt][nt][0] + bv.x, v0y = acc[mt][nt][1] + bv.y;
            float v1x = acc[mt][nt][2] + bv.x, v1y = acc[mt][nt][3] + bv.y;
            if (row0 < M) {
                if (SPLIT_OUT)
                    *(unsigned*)(outh + (size_t)row0 * ostride + col) =
                        packh2(__float2half_rn(v0x), __float2half_rn(v0y));
                *(float2*)(outf + (size_t)row0 * NN + col) = make_float2(v0x, v0y);
            }
            if (row1 < M) {
                if (SPLIT_OUT)
                    *(unsigned*)(outh + (size_t)row1 * ostride + col) =
                        packh2(__float2half_rn(v1x), __float2half_rn(v1y));
                *(float2*)(outf + (size_t)row1 * NN + col) = make_float2(v1x, v1y);
            }
        }
    }
}

// ---------------- final layer + log_softmax ----------------------------------
__global__ void final_kernel(const float* __restrict__ agg,
                             const float* __restrict__ h,
                             const float* __restrict__ Wl,
                             const float* __restrict__ Wr,
                             const float* __restrict__ b,
                             float* __restrict__ out) {
    __shared__ float sWl[H2 * C_OUT], sWr[H2 * C_OUT], sb[C_OUT];
    for (int i = threadIdx.x; i < H2 * C_OUT; i += blockDim.x) {
        sWl[i] = Wl[i];
        sWr[i] = Wr[i];
    }
    if (threadIdx.x < C_OUT) sb[threadIdx.x] = b[threadIdx.x];
    __syncthreads();

    int n = blockIdx.x * blockDim.x + threadIdx.x;
    if (n >= N_NODES) return;

    float logit[C_OUT];
#pragma unroll
    for (int j = 0; j < C_OUT; j++) logit[j] = sb[j];

    const float* ar = agg + (size_t)n * H2;
    const float* hr = h   + (size_t)n * H2;
#pragma unroll 5
    for (int k = 0; k < H2; k++) {
        float a  = ar[k];
        float hh = hr[k];
#pragma unroll
        for (int j = 0; j < C_OUT; j++)
            logit[j] += a * sWl[k * C_OUT + j] + hh * sWr[k * C_OUT + j];
    }

    float mx = logit[0];
#pragma unroll
    for (int j = 1; j < C_OUT; j++) mx = fmaxf(mx, logit[j]);
    float s = 0.0f;
#pragma unroll
    for (int j = 0; j < C_OUT; j++) s += expf(logit[j] - mx);
    float lse = mx + logf(s);
#pragma unroll
    for (int j = 0; j < C_OUT; j++) out[(size_t)n * C_OUT + j] = logit[j] - lse;
}

// ---------------- launch ------------------------------------------------------
extern "C" void kernel_launch(void* const* d_in, const int* in_sizes, int n_in,
                              void* d_out, int out_size) {
    const float* x    = (const float*)d_in[0];
    const int*   ei   = (const int*)d_in[1];
    const float* W_l1 = (const float*)d_in[2];
    const float* b1   = (const float*)d_in[3];
    const float* W_r1 = (const float*)d_in[4];
    const float* W_l2 = (const float*)d_in[5];
    const float* b2   = (const float*)d_in[6];
    const float* W_r2 = (const float*)d_in[7];
    const float* W_l3 = (const float*)d_in[8];
    const float* b3   = (const float*)d_in[9];
    const float* W_r3 = (const float*)d_in[10];
    float* out = (float*)d_out;

    const int* src = ei;
    const int* dst = ei + N_EDGES;

    h16 *xh, *a1h, *h1h, *a2h;
    h16 *w1lh, *w1ll, *w1rh, *w1rl, *w2lh, *w2ll, *w2rh, *w2rl;
    float *h1f, *h2, *agg3;
    cudaGetSymbolAddress((void**)&xh,  g_xh);
    cudaGetSymbolAddress((void**)&a1h, g_a1h);
    cudaGetSymbolAddress((void**)&h1f, g_h1f);
    cudaGetSymbolAddress((void**)&h1h, g_h1h);
    cudaGetSymbolAddress((void**)&a2h, g_a2h);
    cudaGetSymbolAddress((void**)&h2,  g_h2);
    cudaGetSymbolAddress((void**)&agg3, g_agg3);
    cudaGetSymbolAddress((void**)&w1lh, g_w1lh);
    cudaGetSymbolAddress((void**)&w1ll, g_w1ll);
    cudaGetSymbolAddress((void**)&w1rh, g_w1rh);
    cudaGetSymbolAddress((void**)&w1rl, g_w1rl);
    cudaGetSymbolAddress((void**)&w2lh, g_w2lh);
    cudaGetSymbolAddress((void**)&w2ll, g_w2ll);
    cudaGetSymbolAddress((void**)&w2rh, g_w2rh);
    cudaGetSymbolAddress((void**)&w2rl, g_w2rl);

    // smem: stage = A(BM*24) + B hi/lo (BN*24*2), fp16
    const int SMEM1 = 3 * (128 * 24 + 128 * 24 * 2) * 2;   // 55296
    const int SMEM2 = 3 * (128 * 24 + 64 * 24 * 2) * 2;    // 36864
    cudaFuncSetAttribute(gemm_cp<2, 8, true>,
                         cudaFuncAttributeMaxDynamicSharedMemorySize, SMEM1);
    cudaFuncSetAttribute(gemm_cp<2, 4, false>,
                         cudaFuncAttributeMaxDynamicSharedMemorySize, SMEM2);

    prep_kernel<<<(N_NODES * F_IN / 4 + 255) / 256, 256>>>(x, W_l1, W_r1,
                                                           W_l2, W_r2);
    bucket_build_kernel<<<(N_EDGES + 255) / 256, 256>>>(src, dst);

    const int aggBlocks = (N_NODES * 32 + 255) / 256;

    // layer 1: agg x (fp32 gather) -> a1 fp16; GEMM -> h1f fp32 + h1h fp16
    agg_split_kernel<F_IN, F_IN><<<aggBlocks, 256>>>(x, a1h);
    {
        dim3 grid((H1 + 127) / 128, (N_NODES + 127) / 128);
        gemm_cp<2, 8, true><<<grid, 256, SMEM1>>>(
            a1h, xh, w1lh, w1ll, w1rh, w1rl, b1,
            h1f, h1h, N_NODES, F_IN, H1, H1P);
    }

    // layer 2: agg h1f -> a2 fp16 (padded rows); GEMM (K=208) -> h2 fp32
    agg_split_kernel<H1, H1P><<<aggBlocks, 256>>>(h1f, a2h);
    {
        dim3 grid(1, (N_NODES + 127) / 128);
        gemm_cp<2, 4, false><<<grid, 256, SMEM2>>>(
            a2h, h1h, w2lh, w2ll, w2rh, w2rl, b2,
            h2, nullptr, N_NODES, H1P, H2, 0);
    }

    // layer 3 + log_softmax (fp32 path)
    agg_kernel<H2><<<aggBlocks, 256>>>(h2, agg3);
    final_kernel<<<(N_NODES + 255) / 256, 256>>>(agg3, h2, W_l3, W_r3, b3, out);
}

// round 12
// speedup vs baseline: 1.7734x; 1.4153x over previous
#include <cuda_runtime.h>
#include <cuda_fp16.h>
#include <math.h>

#define N_NODES 100000
#define N_EDGES 1600000
#define F_IN   128
#define H1     200
#define H1P    208   // K-padded: fp16 rows 416B, 16B-aligned
#define H2     50
#define C_OUT  10
#define MAXDEG 128

typedef __half h16;

// ---------------- scratch -----------------------------------------------------
__device__ int   g_cnt[N_NODES];
__device__ int   g_bucket[(size_t)N_NODES * MAXDEG];
__device__ h16   g_xh  [(size_t)N_NODES * F_IN];
__device__ h16   g_a1h [(size_t)N_NODES * F_IN];
__device__ h16   g_h1h [(size_t)N_NODES * H1P];
__device__ h16   g_a2h [(size_t)N_NODES * H1P];
__device__ float g_h2  [(size_t)N_NODES * H2];
__device__ float g_agg3[(size_t)N_NODES * H2];
// transposed single-plane fp16 weights [NN, Kpad]
__device__ h16   g_w1l[(size_t)H1 * F_IN], g_w1r[(size_t)H1 * F_IN];
__device__ h16   g_w2l[(size_t)H2 * H1P],  g_w2r[(size_t)H2 * H1P];

__device__ __forceinline__ unsigned packh2(h16 a, h16 b) {
    __half2 p = __halves2half2(a, b);
    return *reinterpret_cast<unsigned*>(&p);
}

// cp.async 16B with zero-fill when !ok
__device__ __forceinline__ void cp16(void* dst, const void* src, bool ok) {
    unsigned d = (unsigned)__cvta_generic_to_shared(dst);
    int ss = ok ? 16 : 0;
    asm volatile("cp.async.ca.shared.global [%0], [%1], 16, %2;"
                 :: "r"(d), "l"(src), "r"(ss));
}
__device__ __forceinline__ void cp_commit() {
    asm volatile("cp.async.commit_group;");
}
__device__ __forceinline__ void cp_wait1() {
    asm volatile("cp.async.wait_group 1;");
}

#define LDSM_X4(r0, r1, r2, r3, addr)                                         \
    asm volatile("ldmatrix.sync.aligned.m8n8.x4.shared.b16 {%0,%1,%2,%3}, [%4];" \
                 : "=r"(r0), "=r"(r1), "=r"(r2), "=r"(r3) : "r"(addr))

__device__ __forceinline__ unsigned sptr(const void* p) {
    return (unsigned)__cvta_generic_to_shared(p);
}

// ---------------- fused prep --------------------------------------------------
__global__ void prep_kernel(const float* __restrict__ x,
                            const float* __restrict__ Wl1,
                            const float* __restrict__ Wr1,
                            const float* __restrict__ Wl2,
                            const float* __restrict__ Wr2) {
    int i = blockIdx.x * blockDim.x + threadIdx.x;
    if (i < N_NODES) g_cnt[i] = 0;
    if (i < N_NODES * F_IN / 4) {           // x -> fp16
        float4 v = ((const float4*)x)[i];
        uint2 uo;
        uo.x = packh2(__float2half_rn(v.x), __float2half_rn(v.y));
        uo.y = packh2(__float2half_rn(v.z), __float2half_rn(v.w));
        *(uint2*)(g_xh + (size_t)i * 4) = uo;
    }
    if (i < H1 * F_IN) {                    // W1 l/r transposed fp16
        int n = i / F_IN, k = i - n * F_IN;
        g_w1l[i] = __float2half_rn(Wl1[(size_t)k * H1 + n]);
        g_w1r[i] = __float2half_rn(Wr1[(size_t)k * H1 + n]);
    }
    if (i < H2 * H1P) {                     // W2 l/r transposed fp16, padded
        int n = i / H1P, k = i - n * H1P;
        float vl = (k < H1) ? Wl2[(size_t)k * H2 + n] : 0.f;
        float vr = (k < H1) ? Wr2[(size_t)k * H2 + n] : 0.f;
        g_w2l[i] = __float2half_rn(vl);
        g_w2r[i] = __float2half_rn(vr);
    }
    if (i < N_NODES * 8) {                  // zero K-pads of h1h / a2h
        int node = i >> 3, kk = H1 + (i & 7);
        g_h1h[(size_t)node * H1P + kk] = __float2half_rn(0.f);
        g_a2h[(size_t)node * H1P + kk] = __float2half_rn(0.f);
    }
}

// ---------------- bucket build ------------------------------------------------
__global__ void bucket_build_kernel(const int* __restrict__ src,
                                    const int* __restrict__ dst) {
    int e = blockIdx.x * blockDim.x + threadIdx.x;
    if (e >= N_EDGES) return;
    int d = dst[e];
    int p = atomicAdd(&g_cnt[d], 1);
    if (p < MAXDEG) g_bucket[(size_t)d * MAXDEG + p] = src[e];
}

// ---------------- fp16 aggregation (max is rounding-commutative) -------------
__device__ __forceinline__ void hmax2_acc(uint2& m, uint2 v) {
    __half2* mp = (__half2*)&m;
    const __half2* vp = (const __half2*)&v;
    mp[0] = __hmax2(mp[0], vp[0]);
    mp[1] = __hmax2(mp[1], vp[1]);
}

// gather fp16 rows (stride STR halves), emit fp16 max (stride STR)
template <int F, int STR>
__global__ void agg_h16_kernel(const h16* __restrict__ x, h16* __restrict__ o) {
    constexpr int C4 = F / 4;               // uint2 = 4 halves per chunk
    constexpr int RV = (C4 + 31) / 32;

    int gwarp = (blockIdx.x * blockDim.x + threadIdx.x) >> 5;
    int lane  = threadIdx.x & 31;
    if (gwarp >= N_NODES) return;

    int c = g_cnt[gwarp];
    if (c > MAXDEG) c = MAXDEG;

    uint2 m[RV];
    {
        h16 ninf = __float2half(-INFINITY);
        unsigned nn = packh2(ninf, ninf);
#pragma unroll
        for (int r = 0; r < RV; r++) { m[r].x = nn; m[r].y = nn; }
    }

    const int* bk = g_bucket + (size_t)gwarp * MAXDEG;
    int i = 0;
    for (; i + 3 < c; i += 4) {
        int s0 = bk[i], s1 = bk[i + 1], s2 = bk[i + 2], s3 = bk[i + 3];
        const uint2* p0 = (const uint2*)(x + (size_t)s0 * STR);
        const uint2* p1 = (const uint2*)(x + (size_t)s1 * STR);
        const uint2* p2 = (const uint2*)(x + (size_t)s2 * STR);
        const uint2* p3 = (const uint2*)(x + (size_t)s3 * STR);
#pragma unroll
        for (int r = 0; r < RV; r++) {
            int ch = lane + r * 32;
            if (ch < C4) {
                uint2 v0 = p0[ch], v1 = p1[ch], v2 = p2[ch], v3 = p3[ch];
                hmax2_acc(v0, v1); hmax2_acc(v2, v3);
                hmax2_acc(v0, v2);
                hmax2_acc(m[r], v0);
            }
        }
    }
    for (; i < c; i++) {
        const uint2* p0 = (const uint2*)(x + (size_t)bk[i] * STR);
#pragma unroll
        for (int r = 0; r < RV; r++) {
            int ch = lane + r * 32;
            if (ch < C4) hmax2_acc(m[r], p0[ch]);
        }
    }

    uint2* out = (uint2*)(o + (size_t)gwarp * STR);
#pragma unroll
    for (int r = 0; r < RV; r++) {
        int ch = lane + r * 32;
        if (ch < C4) out[ch] = (c == 0) ? make_uint2(0u, 0u) : m[r];
    }
}

// ---------------- fp32 aggregation (layer 3, H2=50) --------------------------
__device__ __forceinline__ void fmax2(float2& m, float2 v) {
    m.x = fmaxf(m.x, v.x);
    m.y = fmaxf(m.y, v.y);
}

template <int F>
__global__ void agg_kernel(const float* __restrict__ x, float* __restrict__ agg) {
    constexpr int C2 = F / 2;
    constexpr int RV = (C2 + 31) / 32;

    int gwarp = (blockIdx.x * blockDim.x + threadIdx.x) >> 5;
    int lane  = threadIdx.x & 31;
    if (gwarp >= N_NODES) return;

    int c = g_cnt[gwarp];
    if (c > MAXDEG) c = MAXDEG;

    float2 m[RV];
#pragma unroll
    for (int r = 0; r < RV; r++) { m[r].x = -INFINITY; m[r].y = -INFINITY; }

    const int* bk = g_bucket + (size_t)gwarp * MAXDEG;
    int i = 0;
    for (; i + 3 < c; i += 4) {
        int s0 = bk[i], s1 = bk[i + 1], s2 = bk[i + 2], s3 = bk[i + 3];
        const float2* p0 = (const float2*)(x + (size_t)s0 * F);
        const float2* p1 = (const float2*)(x + (size_t)s1 * F);
        const float2* p2 = (const float2*)(x + (size_t)s2 * F);
        const float2* p3 = (const float2*)(x + (size_t)s3 * F);
#pragma unroll
        for (int r = 0; r < RV; r++) {
            int ch = lane + r * 32;
            if (ch < C2) {
                float2 v0 = p0[ch], v1 = p1[ch], v2 = p2[ch], v3 = p3[ch];
                fmax2(v0, v1); fmax2(v2, v3);
                fmax2(v0, v2);
                fmax2(m[r], v0);
            }
        }
    }
    for (; i < c; i++) {
        const float2* p0 = (const float2*)(x + (size_t)bk[i] * F);
#pragma unroll
        for (int r = 0; r < RV; r++) {
            int ch = lane + r * 32;
            if (ch < C2) fmax2(m[r], p0[ch]);
        }
    }

    float2* out = (float2*)(agg + (size_t)gwarp * F);
#pragma unroll
    for (int r = 0; r < RV; r++) {
        int ch = lane + r * 32;
        if (ch < C2) out[ch] = (c == 0) ? make_float2(0.f, 0.f) : m[r];
    }
}

// ---------------- plain fp16 tensor-core dual GEMM ---------------------------
#define MMAF16(d, a, b0, b1)                                                  \
    asm volatile(                                                             \
        "mma.sync.aligned.m16n8k16.row.col.f32.f16.f16.f32 "                  \
        "{%0,%1,%2,%3}, {%4,%5,%6,%7}, {%8,%9}, {%0,%1,%2,%3};"               \
        : "+f"(d[0]), "+f"(d[1]), "+f"(d[2]), "+f"(d[3])                      \
        : "r"(a[0]), "r"(a[1]), "r"(a[2]), "r"(a[3]), "r"(b0), "r"(b1))

// out = A1@W1 + A2@W2 + bias. A, B single-plane fp16; 1 MMA per product.
// OUT_HALF: store fp16 (outh, stride ostride); else fp32 (outf, stride NN).
template <int WN, int NT, bool OUT_HALF>
__global__ __launch_bounds__(256, 2)
void gemm_s(const h16* __restrict__ A1, const h16* __restrict__ A2,
            const h16* __restrict__ B1, const h16* __restrict__ B2,
            const float* __restrict__ bias,
            float* __restrict__ outf, h16* __restrict__ outh,
            int M, int K, int NN, int ostride) {
    constexpr int WM = 4;
    constexpr int BM = 128;
    constexpr int BN = WN * NT * 8;
    constexpr int LDSTR = 24;
    constexpr int ST = 3;
    static_assert(NT % 2 == 0, "NT must be even");

    extern __shared__ __align__(16) char smem_raw[];
    h16* Ash = (h16*)smem_raw;                  // ST * BM * LDSTR
    h16* Bsh = Ash + ST * BM * LDSTR;           // ST * BN * LDSTR

    int tid = threadIdx.x;
    int lane = tid & 31;
    int wid = tid >> 5;
    int wm = wid % WM;
    int wn = wid / WM;
    int g  = lane >> 2;
    int tg = lane & 3;
    int lr = lane & 15;
    int lc = (lane >> 4) * 8;

    int rowBase = blockIdx.y * BM;
    int colBase = blockIdx.x * BN;

    int npt  = (K + 15) >> 4;
    int totT = 2 * npt;

    const int r_  = tid >> 1;
    const int kh_ = (tid & 1) * 8;
    const int aRow = rowBase + r_;
    const int bn_ = tid >> 1;
    const int gN  = colBase + bn_;

    float acc[2][NT][4];
#pragma unroll
    for (int mt = 0; mt < 2; mt++)
#pragma unroll
        for (int nt = 0; nt < NT; nt++)
#pragma unroll
            for (int q = 0; q < 4; q++) acc[mt][nt][q] = 0.f;

    auto issue = [&](int t, int s) {
        const h16 *A, *B; int ko;
        if (t < npt) { A = A1; B = B1; ko = t << 4; }
        else         { A = A2; B = B2; ko = (t - npt) << 4; }
        int gk = ko + kh_;
        bool okA = (aRow < M) && (gk + 8 <= K);
        cp16(&Ash[s * BM * LDSTR + r_ * LDSTR + kh_],
             okA ? (A + (size_t)aRow * K + gk) : A, okA);
        if (bn_ < BN) {
            bool okB = (gN < NN) && (gk + 8 <= K);
            cp16(&Bsh[s * BN * LDSTR + bn_ * LDSTR + kh_],
                 okB ? (B + (size_t)gN * K + gk) : B, okB);
        }
    };

    auto compute = [&](int s) {
        const h16* As = Ash + s * BM * LDSTR;
        const h16* Bs = Bsh + s * BN * LDSTR;

        unsigned af[2][4];
#pragma unroll
        for (int mt = 0; mt < 2; mt++) {
            int r0 = wm * 32 + mt * 16 + lr;
            LDSM_X4(af[mt][0], af[mt][1], af[mt][2], af[mt][3],
                    sptr(&As[r0 * LDSTR + lc]));
        }

#pragma unroll
        for (int p = 0; p < NT / 2; p++) {
            int rowb = (wn * NT + 2 * p) * 8 + lr;
            unsigned b0, b1, b2, b3;
            LDSM_X4(b0, b1, b2, b3, sptr(&Bs[rowb * LDSTR + lc]));
            MMAF16(acc[0][2 * p],     af[0], b0, b2);
            MMAF16(acc[1][2 * p],     af[1], b0, b2);
            MMAF16(acc[0][2 * p + 1], af[0], b1, b3);
            MMAF16(acc[1][2 * p + 1], af[1], b1, b3);
        }
    };

    issue(0, 0); cp_commit();
    if (totT > 1) issue(1, 1);
    cp_commit();

    for (int t = 0; t < totT; t++) {
        cp_wait1();
        __syncthreads();
        if (t + 2 < totT) issue(t + 2, (t + 2) % ST);
        cp_commit();
        compute(t % ST);
    }

    // ---- epilogue ----
#pragma unroll
    for (int mt = 0; mt < 2; mt++) {
#pragma unroll
        for (int nt = 0; nt < NT; nt++) {
            int col = colBase + (wn * NT + nt) * 8 + 2 * tg;
            if (col >= NN) continue;
            float2 bv = *(const float2*)(bias + col);
            int row0 = rowBase + wm * 32 + mt * 16 + g;
            int row1 = row0 + 8;
            float v0x = acc[mt][nt][0] + bv.x, v0y = acc[mt][nt][1] + bv.y;
            float v1x = acc[mt][nt][2] + bv.x, v1y = acc[mt][nt][3] + bv.y;
            if (row0 < M) {
                if (OUT_HALF)
                    *(unsigned*)(outh + (size_t)row0 * ostride + col) =
                        packh2(__float2half_rn(v0x), __float2half_rn(v0y));
                else
                    *(float2*)(outf + (size_t)row0 * NN + col) =
                        make_float2(v0x, v0y);
            }
            if (row1 < M) {
                if (OUT_HALF)
                    *(unsigned*)(outh + (size_t)row1 * ostride + col) =
                        packh2(__float2half_rn(v1x), __float2half_rn(v1y));
                else
                    *(float2*)(outf + (size_t)row1 * NN + col) =
                        make_float2(v1x, v1y);
            }
        }
    }
}

// ---------------- final layer + log_softmax ----------------------------------
__global__ void final_kernel(const float* __restrict__ agg,
                             const float* __restrict__ h,
                             const float* __restrict__ Wl,
                             const float* __restrict__ Wr,
                             const float* __restrict__ b,
                             float* __restrict__ out) {
    __shared__ float sWl[H2 * C_OUT], sWr[H2 * C_OUT], sb[C_OUT];
    for (int i = threadIdx.x; i < H2 * C_OUT; i += blockDim.x) {
        sWl[i] = Wl[i];
        sWr[i] = Wr[i];
    }
    if (threadIdx.x < C_OUT) sb[threadIdx.x] = b[threadIdx.x];
    __syncthreads();

    int n = blockIdx.x * blockDim.x + threadIdx.x;
    if (n >= N_NODES) return;

    float logit[C_OUT];
#pragma unroll
    for (int j = 0; j < C_OUT; j++) logit[j] = sb[j];

    const float* ar = agg + (size_t)n * H2;
    const float* hr = h   + (size_t)n * H2;
#pragma unroll 5
    for (int k = 0; k < H2; k++) {
        float a  = ar[k];
        float hh = hr[k];
#pragma unroll
        for (int j = 0; j < C_OUT; j++)
            logit[j] += a * sWl[k * C_OUT + j] + hh * sWr[k * C_OUT + j];
    }

    float mx = logit[0];
#pragma unroll
    for (int j = 1; j < C_OUT; j++) mx = fmaxf(mx, logit[j]);
    float s = 0.0f;
#pragma unroll
    for (int j = 0; j < C_OUT; j++) s += expf(logit[j] - mx);
    float lse = mx + logf(s);
#pragma unroll
    for (int j = 0; j < C_OUT; j++) out[(size_t)n * C_OUT + j] = logit[j] - lse;
}

// ---------------- launch ------------------------------------------------------
extern "C" void kernel_launch(void* const* d_in, const int* in_sizes, int n_in,
                              void* d_out, int out_size) {
    const float* x    = (const float*)d_in[0];
    const int*   ei   = (const int*)d_in[1];
    const float* W_l1 = (const float*)d_in[2];
    const float* b1   = (const float*)d_in[3];
    const float* W_r1 = (const float*)d_in[4];
    const float* W_l2 = (const float*)d_in[5];
    const float* b2   = (const float*)d_in[6];
    const float* W_r2 = (const float*)d_in[7];
    const float* W_l3 = (const float*)d_in[8];
    const float* b3   = (const float*)d_in[9];
    const float* W_r3 = (const float*)d_in[10];
    float* out = (float*)d_out;

    const int* src = ei;
    const int* dst = ei + N_EDGES;

    h16 *xh, *a1h, *h1h, *a2h, *w1l, *w1r, *w2l, *w2r;
    float *h2, *agg3;
    cudaGetSymbolAddress((void**)&xh,  g_xh);
    cudaGetSymbolAddress((void**)&a1h, g_a1h);
    cudaGetSymbolAddress((void**)&h1h, g_h1h);
    cudaGetSymbolAddress((void**)&a2h, g_a2h);
    cudaGetSymbolAddress((void**)&h2,  g_h2);
    cudaGetSymbolAddress((void**)&agg3, g_agg3);
    cudaGetSymbolAddress((void**)&w1l, g_w1l);
    cudaGetSymbolAddress((void**)&w1r, g_w1r);
    cudaGetSymbolAddress((void**)&w2l, g_w2l);
    cudaGetSymbolAddress((void**)&w2r, g_w2r);

    const int SMEM1 = 3 * (128 * 24 + 128 * 24) * 2;   // 36864
    const int SMEM2 = 3 * (128 * 24 + 64 * 24) * 2;    // 27648
    cudaFuncSetAttribute(gemm_s<2, 8, true>,
                         cudaFuncAttributeMaxDynamicSharedMemorySize, SMEM1);
    cudaFuncSetAttribute(gemm_s<2, 4, false>,
                         cudaFuncAttributeMaxDynamicSharedMemorySize, SMEM2);

    prep_kernel<<<(N_NODES * F_IN / 4 + 255) / 256, 256>>>(x, W_l1, W_r1,
                                                           W_l2, W_r2);
    bucket_build_kernel<<<(N_EDGES + 255) / 256, 256>>>(src, dst);

    const int aggBlocks = (N_NODES * 32 + 255) / 256;

    // layer 1: agg over xh (fp16, exact) -> a1h; GEMM -> h1h fp16
    agg_h16_kernel<F_IN, F_IN><<<aggBlocks, 256>>>(xh, a1h);
    {
        dim3 grid((H1 + 127) / 128, (N_NODES + 127) / 128);
        gemm_s<2, 8, true><<<grid, 256, SMEM1>>>(
            a1h, xh, w1l, w1r, b1,
            nullptr, h1h, N_NODES, F_IN, H1, H1P);
    }

    // layer 2: agg over h1h (fp16, exact) -> a2h; GEMM (K=208) -> h2 fp32
    agg_h16_kernel<H1, H1P><<<aggBlocks, 256>>>(h1h, a2h);
    {
        dim3 grid(1, (N_NODES + 127) / 128);
        gemm_s<2, 4, false><<<grid, 256, SMEM2>>>(
            a2h, h1h, w2l, w2r, b2,
            h2, nullptr, N_NODES, H1P, H2, 0);
    }

    // layer 3 + log_softmax (fp32 path)
    agg_kernel<H2><<<aggBlocks, 256>>>(h2, agg3);
    final_kernel<<<(N_NODES + 255) / 256, 256>>>(agg3, h2, W_l3, W_r3, b3, out);
}